// round 12
// baseline (speedup 1.0000x reference)
#include <cuda_runtime.h>
#include <cuda_fp16.h>
#include <cstdint>

#define NN 100000
#define NE 1600000
#define DD 128
#define NBLK 391      // ceil(NN/256)
#define NTILE 782     // ceil(NN/128)

// SMEM padded row: 256 halves + 8 pad = 264 halves = 528 bytes (33 x 16B)
#define ROWB 528
#define SMEM_TOT (2 * 128 * ROWB)   // 135168

// ---------------- scratch (static __device__, allocation-free) ----------------
__device__ int    g_is64;
__device__ int    g_deg[NN];
__device__ int    g_local[NN];
__device__ int    g_bsum[NBLK];
__device__ int    g_boff[NBLK];
__device__ int    g_rowptr[NN + 1];
__device__ int    g_cursor[NN];
__device__ int    g_src[NE];
__device__ __half g_xh[(size_t)NN * DD];        // fp16 x cache
__device__ __half g_hh[(size_t)NN * DD];        // fp16 h cache
__device__ __half g_meanh[(size_t)NN * DD];     // fp16 mean
__device__ __half g_Bw0[128 * 256];             // [n][k] fp16: [Wl1;Wr1]
__device__ __half g_Bw1[128 * 256];             // [n][k] fp16: [Wl2;Wr2]

// ---------------- helpers ----------------------------------------------------
__device__ __forceinline__ uint32_t smem_u32(const void* p) {
    uint32_t a;
    asm("{ .reg .u64 t; cvta.to.shared.u64 t, %1; cvt.u32.u64 %0, t; }"
        : "=r"(a) : "l"(p));
    return a;
}
__device__ __forceinline__ void cp_async16(uint32_t smem_addr, const void* gptr) {
    asm volatile("cp.async.cg.shared.global [%0], [%1], 16;"
                 :: "r"(smem_addr), "l"(gptr) : "memory");
}
__device__ __forceinline__ void cp_commit() {
    asm volatile("cp.async.commit_group;" ::: "memory");
}
__device__ __forceinline__ void cp_wait0() {
    asm volatile("cp.async.wait_group 0;" ::: "memory");
}
__device__ __forceinline__ void ldmx4(uint32_t& r0, uint32_t& r1,
                                      uint32_t& r2, uint32_t& r3, uint32_t a) {
    asm volatile("ldmatrix.sync.aligned.m8n8.x4.shared.b16 {%0,%1,%2,%3}, [%4];"
                 : "=r"(r0), "=r"(r1), "=r"(r2), "=r"(r3) : "r"(a));
}
__device__ __forceinline__ void mma16816(float* c, uint32_t a0, uint32_t a1,
                                         uint32_t a2, uint32_t a3,
                                         uint32_t b0, uint32_t b1) {
    asm volatile(
        "mma.sync.aligned.m16n8k16.row.col.f32.f16.f16.f32 "
        "{%0,%1,%2,%3}, {%4,%5,%6,%7}, {%8,%9}, {%0,%1,%2,%3};"
        : "+f"(c[0]), "+f"(c[1]), "+f"(c[2]), "+f"(c[3])
        : "r"(a0), "r"(a1), "r"(a2), "r"(a3), "r"(b0), "r"(b1));
}

// ---------------- dtype detection (int64 vs silently-int32 edge_index) -------
__global__ void k_detect(const void* ei) {
    int t = threadIdx.x;
    long long v = ((const long long*)ei)[t];
    unsigned bad = __ballot_sync(0xFFFFFFFFu, (v < 0) || (v >= NN));
    if (t == 0) g_is64 = (bad == 0) ? 1 : 0;
}
__device__ __forceinline__ int edge_src(const void* ei, int e) {
    return g_is64 ? (int)((const long long*)ei)[e] : ((const int*)ei)[e];
}
__device__ __forceinline__ int edge_dst(const void* ei, int e) {
    return g_is64 ? (int)((const long long*)ei)[(size_t)NE + e]
                  : ((const int*)ei)[(size_t)NE + e];
}

// ---------------- fp32 -> fp16 x cache ---------------------------------------
__global__ void __launch_bounds__(256) k_tohalf(const float* __restrict__ in,
                                                __half* __restrict__ outp) {
    int i = blockIdx.x * blockDim.x + threadIdx.x;
    if (i >= NN * DD / 4) return;
    float4 v = ((const float4*)in)[i];
    __half2 a = __floats2half2_rn(v.x, v.y);
    __half2 b = __floats2half2_rn(v.z, v.w);
    uint2 u;
    u.x = *reinterpret_cast<unsigned*>(&a);
    u.y = *reinterpret_cast<unsigned*>(&b);
    ((uint2*)outp)[i] = u;
}

// ---------------- weight prep: fp16 B[n][k] = [Wl;Wr] transposed -------------
__global__ void __launch_bounds__(256) k_prepB(const float* __restrict__ Wl1,
                                               const float* __restrict__ Wr1,
                                               const float* __restrict__ Wl2,
                                               const float* __restrict__ Wr2) {
    int idx = blockIdx.x * blockDim.x + threadIdx.x;   // 65536 total
    if (idx >= 2 * 128 * 256) return;
    int layer = idx >> 15;
    int rem = idx & 32767;
    int n = rem >> 8;
    int k = rem & 255;
    const float* Wl = layer ? Wl2 : Wl1;
    const float* Wr = layer ? Wr2 : Wr1;
    float v = (k < 128) ? Wl[k * 128 + n] : Wr[(k - 128) * 128 + n];
    (layer ? g_Bw1 : g_Bw0)[n * 256 + k] = __float2half_rn(v);
}

// ---------------- CSR build ----------------
__global__ void k_zero_deg() {
    int i = blockIdx.x * blockDim.x + threadIdx.x;
    if (i < NN) g_deg[i] = 0;
}
__global__ void k_degree(const void* ei) {
    int e = blockIdx.x * blockDim.x + threadIdx.x;
    if (e >= NE) return;
    atomicAdd(&g_deg[edge_dst(ei, e)], 1);
}
__global__ void __launch_bounds__(256) k_scan1() {
    __shared__ int ws[8];
    int b = blockIdx.x, t = threadIdx.x;
    int i = b * 256 + t;
    int v = (i < NN) ? g_deg[i] : 0;
    int x = v;
#pragma unroll
    for (int o = 1; o < 32; o <<= 1) {
        int y = __shfl_up_sync(0xFFFFFFFFu, x, o);
        if ((t & 31) >= o) x += y;
    }
    if ((t & 31) == 31) ws[t >> 5] = x;
    __syncthreads();
    if (t < 8) {
        int y = ws[t];
#pragma unroll
        for (int o = 1; o < 8; o <<= 1) {
            int z = __shfl_up_sync(0x000000FFu, y, o);
            if (t >= o) y += z;
        }
        ws[t] = y;
    }
    __syncthreads();
    int incl = x + ((t >= 32) ? ws[(t >> 5) - 1] : 0);
    if (i < NN) g_local[i] = incl - v;
    if (t == 255) g_bsum[b] = incl;
}
__global__ void __launch_bounds__(512) k_scan2() {
    __shared__ int ws[16];
    int t = threadIdx.x;
    int v = (t < NBLK) ? g_bsum[t] : 0;
    int x = v;
#pragma unroll
    for (int o = 1; o < 32; o <<= 1) {
        int y = __shfl_up_sync(0xFFFFFFFFu, x, o);
        if ((t & 31) >= o) x += y;
    }
    if ((t & 31) == 31) ws[t >> 5] = x;
    __syncthreads();
    if (t < 16) {
        int y = ws[t];
#pragma unroll
        for (int o = 1; o < 16; o <<= 1) {
            int z = __shfl_up_sync(0x0000FFFFu, y, o);
            if (t >= o) y += z;
        }
        ws[t] = y;
    }
    __syncthreads();
    int incl = x + ((t >= 32) ? ws[(t >> 5) - 1] : 0);
    if (t < NBLK) g_boff[t] = incl - v;
    if (t == NBLK - 1) g_rowptr[NN] = incl;
}
__global__ void k_scan3() {
    int i = blockIdx.x * blockDim.x + threadIdx.x;
    if (i >= NN) return;
    int r = g_boff[i >> 8] + g_local[i];
    g_rowptr[i] = r;
    g_cursor[i] = r;
}
__global__ void k_fill(const void* ei) {
    int e = blockIdx.x * blockDim.x + threadIdx.x;
    if (e >= NE) return;
    int s = edge_src(ei, e);
    int d = edge_dst(ei, e);
    int pos = atomicAdd(&g_cursor[d], 1);
    g_src[pos] = s;
}

// ---------------- mean aggregation via cp.async gather -----------------------
// Warp per node. Per 16-edge batch: 8 cp.async.cg warp-instructions (16B/lane;
// lanes 0-15 stage edge j, lanes 16-31 edge j+1) gather 16 rows (4KB) into the
// warp's smem buffer — fire-and-forget, no register landing, no L1-miss slots.
// Then accumulate from smem in fp32 (two chains), same arithmetic as before.
__global__ void __launch_bounds__(256) k_aggh(const __half* __restrict__ in,
                                              __half* __restrict__ outp) {
    __shared__ __align__(16) char buf[8][4096];   // 16 edges x 256B per warp
    int gwarp = (blockIdx.x * blockDim.x + threadIdx.x) >> 5;
    int wl = threadIdx.x >> 5;
    int lane = threadIdx.x & 31;
    int l16 = lane & 15, eoff = lane >> 4;
    if (gwarp >= NN) return;
    int beg = g_rowptr[gwarp];
    int end = g_rowptr[gwarp + 1];
    uint32_t sb = smem_u32(buf[wl]);
    const char* inb = (const char*)in;            // row = 256B
    float acc0[4] = {0.f, 0.f, 0.f, 0.f};
    float acc1[4] = {0.f, 0.f, 0.f, 0.f};

    int e = beg;
    while (e < end) {
        int nb = end - e;
        if (nb > 16) nb = 16;
        // stage nb rows (2 edges per cp.async instruction)
        for (int j = 0; j < nb; j += 2) {
            int idx = j + eoff;
            if (idx < nb) {
                int s = g_src[e + idx];
                cp_async16(sb + idx * 256 + l16 * 16,
                           inb + (size_t)s * 256 + l16 * 16);
            }
        }
        cp_commit();
        cp_wait0();
        __syncwarp();
        // accumulate nb rows; lane owns bytes [lane*8, lane*8+8) = 4 halves
#define ACCUM(ACC, U)                                                         \
        {                                                                     \
            float2 lo = __half22float2(*reinterpret_cast<__half2*>(&(U).x));  \
            float2 hi = __half22float2(*reinterpret_cast<__half2*>(&(U).y));  \
            ACC[0] += lo.x; ACC[1] += lo.y; ACC[2] += hi.x; ACC[3] += hi.y;   \
        }
        int j = 0;
        for (; j + 2 <= nb; j += 2) {
            uint2 u0 = *(uint2*)(buf[wl] + j * 256 + lane * 8);
            uint2 u1 = *(uint2*)(buf[wl] + (j + 1) * 256 + lane * 8);
            ACCUM(acc0, u0)
            ACCUM(acc1, u1)
        }
        if (j < nb) {
            uint2 u = *(uint2*)(buf[wl] + j * 256 + lane * 8);
            ACCUM(acc0, u)
        }
#undef ACCUM
        __syncwarp();     // buffer reuse barrier
        e += nb;
    }

    int deg = end - beg;
    float inv = 1.0f / (float)(deg > 0 ? deg : 1);
    __half2 a = __floats2half2_rn((acc0[0] + acc1[0]) * inv,
                                  (acc0[1] + acc1[1]) * inv);
    __half2 b = __floats2half2_rn((acc0[2] + acc1[2]) * inv,
                                  (acc0[3] + acc1[3]) * inv);
    uint2 u;
    u.x = *reinterpret_cast<unsigned*>(&a);
    u.y = *reinterpret_cast<unsigned*>(&b);
    ((uint2*)outp)[(size_t)gwarp * 32 + lane] = u;
}

// ---------------- HMMA fused dual-GEMM ---------------------------------------
// Per CTA: 128-node tile. A = [mean | x] fp16 (128 x 256), B = [Wl;Wr] fp16
// (128 x 256, [n][k]). 8 warps = 8 m16 tiles; per warp 16 n8 tiles, 16 k16
// steps of mma.sync.m16n8k16 f32 accum. Rows padded to 528B in SMEM ->
// conflict-free ldmatrix.
__global__ void __launch_bounds__(256) k_gemm(const __half* __restrict__ Am,
                                              const __half* __restrict__ Ax,
                                              const __half* __restrict__ Bw,
                                              const float* __restrict__ bias,
                                              float* __restrict__ outp,
                                              __half* __restrict__ outh,
                                              int doRelu) {
    extern __shared__ char smem[];
    char* As = smem;                         // 128 rows x 528B
    char* Bs = smem + 128 * ROWB;            // 128 rows x 528B
    int tid = threadIdx.x;
    int wid = tid >> 5, lane = tid & 31;
    int node0 = blockIdx.x * 128;

    // Stage B (weights): row n, 32 x 16B chunks.
    {
        const uint4* bsrc = (const uint4*)Bw;
        for (int t = tid; t < 4096; t += 256) {
            int row = t >> 5, c = t & 31;
            *(uint4*)(Bs + row * ROWB + c * 16) = bsrc[row * 32 + c];
        }
    }
    // Stage A: [mean | x] per node row.
    for (int t = tid; t < 4096; t += 256) {
        int row = t >> 5, c = t & 31;
        int node = node0 + row;
        uint4 v = make_uint4(0, 0, 0, 0);
        if (node < NN) {
            v = (c < 16)
                ? ((const uint4*)(Am + (size_t)node * 128))[c]
                : ((const uint4*)(Ax + (size_t)node * 128))[c - 16];
        }
        *(uint4*)(As + row * ROWB + c * 16) = v;
    }
    __syncthreads();

    int m0 = wid * 16;
    uint32_t aaddr = smem_u32(As) + (m0 + (lane & 15)) * ROWB + ((lane >> 4) * 8) * 2;
    uint32_t baddr = smem_u32(Bs) + ((lane & 7) + ((lane >> 4) << 3)) * ROWB +
                     (((lane >> 3) & 1) * 8) * 2;

    float c[16][4];
#pragma unroll
    for (int i = 0; i < 16; i++)
#pragma unroll
        for (int j = 0; j < 4; j++) c[i][j] = 0.f;

#pragma unroll
    for (int k0 = 0; k0 < 256; k0 += 16) {
        uint32_t a0, a1, a2, a3;
        ldmx4(a0, a1, a2, a3, aaddr + k0 * 2);
#pragma unroll
        for (int p = 0; p < 8; p++) {
            uint32_t b0, b1, b2, b3;
            ldmx4(b0, b1, b2, b3, baddr + p * 16 * ROWB + k0 * 2);
            mma16816(c[2 * p],     a0, a1, a2, a3, b0, b1);
            mma16816(c[2 * p + 1], a0, a1, a2, a3, b2, b3);
        }
    }

    // Epilogue: c[nt] -> rows (m0+gID, m0+gID+8), cols nt*8 + 2*tig (+1)
    int gID = lane >> 2, tig = lane & 3;
    int nodeA = node0 + m0 + gID;
    int nodeB = nodeA + 8;
#pragma unroll
    for (int nt = 0; nt < 16; nt++) {
        int col = nt * 8 + 2 * tig;
        float2 bb = *(const float2*)(bias + col);
        float v0 = c[nt][0] + bb.x, v1 = c[nt][1] + bb.y;
        float v2 = c[nt][2] + bb.x, v3 = c[nt][3] + bb.y;
        if (doRelu) {
            v0 = fmaxf(v0, 0.f); v1 = fmaxf(v1, 0.f);
            v2 = fmaxf(v2, 0.f); v3 = fmaxf(v3, 0.f);
        }
        if (nodeA < NN) {
            if (outp) ((float2*)outp)[(size_t)nodeA * 64 + nt * 4 + tig] =
                make_float2(v0, v1);
            if (outh) {
                __half2 hh = __floats2half2_rn(v0, v1);
                ((__half2*)outh)[(size_t)nodeA * 64 + nt * 4 + tig] = hh;
            }
        }
        if (nodeB < NN) {
            if (outp) ((float2*)outp)[(size_t)nodeB * 64 + nt * 4 + tig] =
                make_float2(v2, v3);
            if (outh) {
                __half2 hh = __floats2half2_rn(v2, v3);
                ((__half2*)outh)[(size_t)nodeB * 64 + nt * 4 + tig] = hh;
            }
        }
    }
}

// ---------------- launch ----------------
extern "C" void kernel_launch(void* const* d_in, const int* in_sizes, int n_in,
                              void* d_out, int out_size) {
    const float* x   = (const float*)d_in[0];
    const void*  ei  = d_in[1];
    const float* Wl1 = (const float*)d_in[2];
    const float* Wr1 = (const float*)d_in[3];
    const float* b1  = (const float*)d_in[4];
    const float* Wl2 = (const float*)d_in[5];
    const float* Wr2 = (const float*)d_in[6];
    const float* b2  = (const float*)d_in[7];
    float* out = (float*)d_out;

    cudaFuncSetAttribute(k_gemm, cudaFuncAttributeMaxDynamicSharedMemorySize,
                         SMEM_TOT);

    void *p_xh, *p_hh, *p_mh, *p_b0, *p_b1;
    cudaGetSymbolAddress(&p_xh, g_xh);
    cudaGetSymbolAddress(&p_hh, g_hh);
    cudaGetSymbolAddress(&p_mh, g_meanh);
    cudaGetSymbolAddress(&p_b0, g_Bw0);
    cudaGetSymbolAddress(&p_b1, g_Bw1);
    __half* xh = (__half*)p_xh;
    __half* hh = (__half*)p_hh;
    __half* mh = (__half*)p_mh;
    __half* B0 = (__half*)p_b0;
    __half* B1 = (__half*)p_b1;

    // CSR build + fp16 caches + weight prep
    k_detect<<<1, 32>>>(ei);
    k_zero_deg<<<(NN + 255) / 256, 256>>>();
    k_tohalf<<<(NN * DD / 4 + 255) / 256, 256>>>(x, xh);
    k_degree<<<(NE + 255) / 256, 256>>>(ei);
    k_prepB<<<256, 256>>>(Wl1, Wr1, Wl2, Wr2);
    k_scan1<<<NBLK, 256>>>();
    k_scan2<<<1, 512>>>();
    k_scan3<<<(NN + 255) / 256, 256>>>();
    k_fill<<<(NE + 255) / 256, 256>>>(ei);

    // Layer 1: agg(xh) -> meanh; GEMM -> hh (fp16, relu)
    k_aggh<<<(NN + 7) / 8, 256>>>(xh, mh);
    k_gemm<<<NTILE, 256, SMEM_TOT>>>(mh, xh, B0, b1, (float*)nullptr, hh, 1);

    // Layer 2: agg(hh) -> meanh; GEMM -> d_out (fp32)
    k_aggh<<<(NN + 7) / 8, 256>>>(hh, mh);
    k_gemm<<<NTILE, 256, SMEM_TOT>>>(mh, hh, B1, b2, out, (__half*)nullptr, 0);
}

// round 14
// speedup vs baseline: 1.5831x; 1.5831x over previous
#include <cuda_runtime.h>
#include <cuda_fp16.h>
#include <cstdint>

#define NN 100000
#define NE 1600000
#define DD 128
#define NBLK 391      // ceil(NN/256)
#define NTILE 782     // ceil(NN/128)

// SMEM padded row: 256 halves + 8 pad = 264 halves = 528 bytes (33 x 16B)
#define ROWB 528
#define SMEM_TOT (2 * 128 * ROWB)   // 135168

// ---------------- scratch (static __device__, allocation-free) ----------------
__device__ int    g_is64;
__device__ int    g_deg[NN];
__device__ int    g_local[NN];
__device__ int    g_bsum[NBLK];
__device__ int    g_boff[NBLK];
__device__ int    g_rowptr[NN + 1];
__device__ int    g_src32[NE];                  // decoded src
__device__ int    g_dst32[NE];                  // decoded dst
__device__ int    g_pos[NE];                    // slot within dst's list
__device__ int    g_src[NE];                    // CSR adjacency
__device__ __half g_xh[(size_t)NN * DD];        // fp16 x cache
__device__ __half g_hh[(size_t)NN * DD];        // fp16 h cache
__device__ __half g_meanh[(size_t)NN * DD];     // fp16 mean
__device__ __half g_Bw0[128 * 256];             // [n][k] fp16: [Wl1;Wr1]
__device__ __half g_Bw1[128 * 256];             // [n][k] fp16: [Wl2;Wr2]

// ---------------- helpers ----------------------------------------------------
__device__ __forceinline__ uint32_t smem_u32(const void* p) {
    uint32_t a;
    asm("{ .reg .u64 t; cvta.to.shared.u64 t, %1; cvt.u32.u64 %0, t; }"
        : "=r"(a) : "l"(p));
    return a;
}
__device__ __forceinline__ void ldmx4(uint32_t& r0, uint32_t& r1,
                                      uint32_t& r2, uint32_t& r3, uint32_t a) {
    asm volatile("ldmatrix.sync.aligned.m8n8.x4.shared.b16 {%0,%1,%2,%3}, [%4];"
                 : "=r"(r0), "=r"(r1), "=r"(r2), "=r"(r3) : "r"(a));
}
__device__ __forceinline__ void mma16816(float* c, uint32_t a0, uint32_t a1,
                                         uint32_t a2, uint32_t a3,
                                         uint32_t b0, uint32_t b1) {
    asm volatile(
        "mma.sync.aligned.m16n8k16.row.col.f32.f16.f16.f32 "
        "{%0,%1,%2,%3}, {%4,%5,%6,%7}, {%8,%9}, {%0,%1,%2,%3};"
        : "+f"(c[0]), "+f"(c[1]), "+f"(c[2]), "+f"(c[3])
        : "r"(a0), "r"(a1), "r"(a2), "r"(a3), "r"(b0), "r"(b1));
}

// ---------------- dtype helpers ----------------------------------------------
__device__ __forceinline__ int edge_src(const void* ei, int e) {
    return g_is64 ? (int)((const long long*)ei)[e] : ((const int*)ei)[e];
}
__device__ __forceinline__ int edge_dst(const void* ei, int e) {
    return g_is64 ? (int)((const long long*)ei)[(size_t)NE + e]
                  : ((const int*)ei)[(size_t)NE + e];
}

// ---------------- fused prep: detect dtype + zero degrees + weight transpose -
// Block 0 / warp 0: int64-vs-int32 detection (ballot over 32 leading values).
// All threads: zero g_deg (i < NN) and build fp16 [n][k] weight copies
// (i < 2*128*256). Grid = NBLK x 256 (100096 threads >= both ranges... prepB
// needs 65536, zero needs 100000 -> both covered).
__global__ void __launch_bounds__(256) k_prep0(const void* ei,
                                               const float* __restrict__ Wl1,
                                               const float* __restrict__ Wr1,
                                               const float* __restrict__ Wl2,
                                               const float* __restrict__ Wr2) {
    int i = blockIdx.x * blockDim.x + threadIdx.x;
    if (blockIdx.x == 0 && threadIdx.x < 32) {
        long long v = ((const long long*)ei)[threadIdx.x];
        unsigned bad = __ballot_sync(0xFFFFFFFFu, (v < 0) || (v >= NN));
        if (threadIdx.x == 0) g_is64 = (bad == 0) ? 1 : 0;
    }
    if (i < NN) g_deg[i] = 0;
    if (i < 2 * 128 * 256) {
        int layer = i >> 15;
        int rem = i & 32767;
        int n = rem >> 8;
        int k = rem & 255;
        const float* Wl = layer ? Wl2 : Wl1;
        const float* Wr = layer ? Wr2 : Wr1;
        float v = (k < 128) ? Wl[k * 128 + n] : Wr[(k - 128) * 128 + n];
        (layer ? g_Bw1 : g_Bw0)[n * 256 + k] = __float2half_rn(v);
    }
}

// ---------------- degree pass (+ decode + slot stash + x->fp16 fold) ---------
// Per edge: decode (src,dst) once to int32, count degree, remember the slot
// this edge got (kills the second atomic pass). Each thread also converts two
// float4 of x to fp16 (2 * NE == NN*DD/4 exactly covers the tensor).
__global__ void __launch_bounds__(256) k_degree2(const void* ei,
                                                 const float* __restrict__ x,
                                                 __half* __restrict__ xh) {
    int e = blockIdx.x * blockDim.x + threadIdx.x;
    if (e < NE) {
        int s = edge_src(ei, e);
        int d = edge_dst(ei, e);
        g_src32[e] = s;
        g_dst32[e] = d;
        g_pos[e] = atomicAdd(&g_deg[d], 1);
    }
#pragma unroll
    for (int r = 0; r < 2; r++) {
        int i = e + r * NE;
        if (i < NN * DD / 4) {
            float4 v = ((const float4*)x)[i];
            __half2 a = __floats2half2_rn(v.x, v.y);
            __half2 b = __floats2half2_rn(v.z, v.w);
            uint2 u;
            u.x = *reinterpret_cast<unsigned*>(&a);
            u.y = *reinterpret_cast<unsigned*>(&b);
            ((uint2*)xh)[i] = u;
        }
    }
}

// ---------------- 3-phase parallel exclusive scan over degrees ---------------
__global__ void __launch_bounds__(256) k_scan1() {
    __shared__ int ws[8];
    int b = blockIdx.x, t = threadIdx.x;
    int i = b * 256 + t;
    int v = (i < NN) ? g_deg[i] : 0;
    int x = v;
#pragma unroll
    for (int o = 1; o < 32; o <<= 1) {
        int y = __shfl_up_sync(0xFFFFFFFFu, x, o);
        if ((t & 31) >= o) x += y;
    }
    if ((t & 31) == 31) ws[t >> 5] = x;
    __syncthreads();
    if (t < 8) {
        int y = ws[t];
#pragma unroll
        for (int o = 1; o < 8; o <<= 1) {
            int z = __shfl_up_sync(0x000000FFu, y, o);
            if (t >= o) y += z;
        }
        ws[t] = y;
    }
    __syncthreads();
    int incl = x + ((t >= 32) ? ws[(t >> 5) - 1] : 0);
    if (i < NN) g_local[i] = incl - v;
    if (t == 255) g_bsum[b] = incl;
}
__global__ void __launch_bounds__(512) k_scan2() {
    __shared__ int ws[16];
    int t = threadIdx.x;
    int v = (t < NBLK) ? g_bsum[t] : 0;
    int x = v;
#pragma unroll
    for (int o = 1; o < 32; o <<= 1) {
        int y = __shfl_up_sync(0xFFFFFFFFu, x, o);
        if ((t & 31) >= o) x += y;
    }
    if ((t & 31) == 31) ws[t >> 5] = x;
    __syncthreads();
    if (t < 16) {
        int y = ws[t];
#pragma unroll
        for (int o = 1; o < 16; o <<= 1) {
            int z = __shfl_up_sync(0x0000FFFFu, y, o);
            if (t >= o) y += z;
        }
        ws[t] = y;
    }
    __syncthreads();
    int incl = x + ((t >= 32) ? ws[(t >> 5) - 1] : 0);
    if (t < NBLK) g_boff[t] = incl - v;
    if (t == NBLK - 1) g_rowptr[NN] = incl;
}
__global__ void k_scan3() {
    int i = blockIdx.x * blockDim.x + threadIdx.x;
    if (i >= NN) return;
    g_rowptr[i] = g_boff[i >> 8] + g_local[i];
}

// ---------------- CSR fill (atomic-free; slot stashed in degree pass) --------
__global__ void __launch_bounds__(256) k_fillp() {
    int e = blockIdx.x * blockDim.x + threadIdx.x;
    if (e >= NE) return;
    int d = g_dst32[e];
    g_src[g_rowptr[d] + g_pos[e]] = g_src32[e];
}

// ---------------- mean aggregation: warp per node (R8 configuration) ---------
// Lane owns one uint2 (4 halves) of the 256B row; 8-edge unroll with two
// fp32 accumulator chains.
__global__ void __launch_bounds__(256) k_aggh(const __half* __restrict__ in,
                                              __half* __restrict__ outp) {
    int warp = (blockIdx.x * blockDim.x + threadIdx.x) >> 5;
    int lane = threadIdx.x & 31;
    if (warp >= NN) return;
    int beg = g_rowptr[warp];
    int end = g_rowptr[warp + 1];
    const uint2* iv = (const uint2*)in;
    float4 acc0 = make_float4(0.f, 0.f, 0.f, 0.f);
    float4 acc1 = make_float4(0.f, 0.f, 0.f, 0.f);
    int e = beg;
    for (; e + 8 <= end; e += 8) {
        int s0 = g_src[e],     s1 = g_src[e + 1], s2 = g_src[e + 2], s3 = g_src[e + 3];
        int s4 = g_src[e + 4], s5 = g_src[e + 5], s6 = g_src[e + 6], s7 = g_src[e + 7];
        uint2 u0 = iv[s0 * 32 + lane];
        uint2 u1 = iv[s1 * 32 + lane];
        uint2 u2 = iv[s2 * 32 + lane];
        uint2 u3 = iv[s3 * 32 + lane];
        uint2 u4 = iv[s4 * 32 + lane];
        uint2 u5 = iv[s5 * 32 + lane];
        uint2 u6 = iv[s6 * 32 + lane];
        uint2 u7 = iv[s7 * 32 + lane];
#define ACCUM(ACC, U)                                                         \
        {                                                                     \
            float2 lo = __half22float2(*reinterpret_cast<__half2*>(&(U).x));  \
            float2 hi = __half22float2(*reinterpret_cast<__half2*>(&(U).y));  \
            ACC.x += lo.x; ACC.y += lo.y; ACC.z += hi.x; ACC.w += hi.y;       \
        }
        ACCUM(acc0, u0) ACCUM(acc0, u1) ACCUM(acc0, u2) ACCUM(acc0, u3)
        ACCUM(acc1, u4) ACCUM(acc1, u5) ACCUM(acc1, u6) ACCUM(acc1, u7)
    }
    for (; e < end; e++) {
        uint2 u = iv[g_src[e] * 32 + lane];
        ACCUM(acc0, u)
    }
#undef ACCUM
    int deg = end - beg;
    float inv = 1.0f / (float)(deg > 0 ? deg : 1);
    __half2 a = __floats2half2_rn((acc0.x + acc1.x) * inv, (acc0.y + acc1.y) * inv);
    __half2 b = __floats2half2_rn((acc0.z + acc1.z) * inv, (acc0.w + acc1.w) * inv);
    uint2 u;
    u.x = *reinterpret_cast<unsigned*>(&a);
    u.y = *reinterpret_cast<unsigned*>(&b);
    ((uint2*)outp)[warp * 32 + lane] = u;
}

// ---------------- HMMA fused dual-GEMM ---------------------------------------
__global__ void __launch_bounds__(256) k_gemm(const __half* __restrict__ Am,
                                              const __half* __restrict__ Ax,
                                              const __half* __restrict__ Bw,
                                              const float* __restrict__ bias,
                                              float* __restrict__ outp,
                                              __half* __restrict__ outh,
                                              int doRelu) {
    extern __shared__ char smem[];
    char* As = smem;                         // 128 rows x 528B
    char* Bs = smem + 128 * ROWB;            // 128 rows x 528B
    int tid = threadIdx.x;
    int wid = tid >> 5, lane = tid & 31;
    int node0 = blockIdx.x * 128;

    {
        const uint4* bsrc = (const uint4*)Bw;
        for (int t = tid; t < 4096; t += 256) {
            int row = t >> 5, c = t & 31;
            *(uint4*)(Bs + row * ROWB + c * 16) = bsrc[row * 32 + c];
        }
    }
    for (int t = tid; t < 4096; t += 256) {
        int row = t >> 5, c = t & 31;
        int node = node0 + row;
        uint4 v = make_uint4(0, 0, 0, 0);
        if (node < NN) {
            v = (c < 16)
                ? ((const uint4*)(Am + (size_t)node * 128))[c]
                : ((const uint4*)(Ax + (size_t)node * 128))[c - 16];
        }
        *(uint4*)(As + row * ROWB + c * 16) = v;
    }
    __syncthreads();

    int m0 = wid * 16;
    uint32_t aaddr = smem_u32(As) + (m0 + (lane & 15)) * ROWB + ((lane >> 4) * 8) * 2;
    uint32_t baddr = smem_u32(Bs) + ((lane & 7) + ((lane >> 4) << 3)) * ROWB +
                     (((lane >> 3) & 1) * 8) * 2;

    float c[16][4];
#pragma unroll
    for (int i = 0; i < 16; i++)
#pragma unroll
        for (int j = 0; j < 4; j++) c[i][j] = 0.f;

#pragma unroll
    for (int k0 = 0; k0 < 256; k0 += 16) {
        uint32_t a0, a1, a2, a3;
        ldmx4(a0, a1, a2, a3, aaddr + k0 * 2);
#pragma unroll
        for (int p = 0; p < 8; p++) {
            uint32_t b0, b1, b2, b3;
            ldmx4(b0, b1, b2, b3, baddr + p * 16 * ROWB + k0 * 2);
            mma16816(c[2 * p],     a0, a1, a2, a3, b0, b1);
            mma16816(c[2 * p + 1], a0, a1, a2, a3, b2, b3);
        }
    }

    int gID = lane >> 2, tig = lane & 3;
    int nodeA = node0 + m0 + gID;
    int nodeB = nodeA + 8;
#pragma unroll
    for (int nt = 0; nt < 16; nt++) {
        int col = nt * 8 + 2 * tig;
        float2 bb = *(const float2*)(bias + col);
        float v0 = c[nt][0] + bb.x, v1 = c[nt][1] + bb.y;
        float v2 = c[nt][2] + bb.x, v3 = c[nt][3] + bb.y;
        if (doRelu) {
            v0 = fmaxf(v0, 0.f); v1 = fmaxf(v1, 0.f);
            v2 = fmaxf(v2, 0.f); v3 = fmaxf(v3, 0.f);
        }
        if (nodeA < NN) {
            if (outp) ((float2*)outp)[(size_t)nodeA * 64 + nt * 4 + tig] =
                make_float2(v0, v1);
            if (outh) {
                __half2 hh = __floats2half2_rn(v0, v1);
                ((__half2*)outh)[(size_t)nodeA * 64 + nt * 4 + tig] = hh;
            }
        }
        if (nodeB < NN) {
            if (outp) ((float2*)outp)[(size_t)nodeB * 64 + nt * 4 + tig] =
                make_float2(v2, v3);
            if (outh) {
                __half2 hh = __floats2half2_rn(v2, v3);
                ((__half2*)outh)[(size_t)nodeB * 64 + nt * 4 + tig] = hh;
            }
        }
    }
}

// ---------------- launch ----------------
extern "C" void kernel_launch(void* const* d_in, const int* in_sizes, int n_in,
                              void* d_out, int out_size) {
    const float* x   = (const float*)d_in[0];
    const void*  ei  = d_in[1];
    const float* Wl1 = (const float*)d_in[2];
    const float* Wr1 = (const float*)d_in[3];
    const float* b1  = (const float*)d_in[4];
    const float* Wl2 = (const float*)d_in[5];
    const float* Wr2 = (const float*)d_in[6];
    const float* b2  = (const float*)d_in[7];
    float* out = (float*)d_out;

    cudaFuncSetAttribute(k_gemm, cudaFuncAttributeMaxDynamicSharedMemorySize,
                         SMEM_TOT);

    void *p_xh, *p_hh, *p_mh, *p_b0, *p_b1;
    cudaGetSymbolAddress(&p_xh, g_xh);
    cudaGetSymbolAddress(&p_hh, g_hh);
    cudaGetSymbolAddress(&p_mh, g_meanh);
    cudaGetSymbolAddress(&p_b0, g_Bw0);
    cudaGetSymbolAddress(&p_b1, g_Bw1);
    __half* xh = (__half*)p_xh;
    __half* hh = (__half*)p_hh;
    __half* mh = (__half*)p_mh;
    __half* B0 = (__half*)p_b0;
    __half* B1 = (__half*)p_b1;

    // Prep + CSR build (10 launches total)
    k_prep0<<<NBLK, 256>>>(ei, Wl1, Wr1, Wl2, Wr2);
    k_degree2<<<(NE + 255) / 256, 256>>>(ei, x, xh);
    k_scan1<<<NBLK, 256>>>();
    k_scan2<<<1, 512>>>();
    k_scan3<<<(NN + 255) / 256, 256>>>();
    k_fillp<<<(NE + 255) / 256, 256>>>();

    // Layer 1: agg(xh) -> meanh; GEMM -> hh (fp16, relu)
    k_aggh<<<(NN + 7) / 8, 256>>>(xh, mh);
    k_gemm<<<NTILE, 256, SMEM_TOT>>>(mh, xh, B0, b1, (float*)nullptr, hh, 1);

    // Layer 2: agg(hh) -> meanh; GEMM -> d_out (fp32)
    k_aggh<<<(NN + 7) / 8, 256>>>(hh, mh);
    k_gemm<<<NTILE, 256, SMEM_TOT>>>(mh, hh, B1, b2, out, (__half*)nullptr, 0);
}